// round 1
// baseline (speedup 1.0000x reference)
#include <cuda_runtime.h>
#include <cuda_bf16.h>

#define D_DIM 256
#define N_MAX 16384
#define K_MAX 8192

#define BM 64
#define BN 128
#define BK 16
#define TM 8
#define TN 8
#define NTHREADS 128   // (BN/TN)=16 cols x (BM/TM)=8 rows

// Scratch (allocation-free rule: device globals)
__device__ float g_xsq[N_MAX];
__device__ float g_esq[K_MAX];

// -------- sum-of-squares per row, warp per row --------
__global__ void sumsq_kernel(const float* __restrict__ x, float* __restrict__ out, int rows) {
    int warps_per_blk = blockDim.x >> 5;
    int row = blockIdx.x * warps_per_blk + (threadIdx.x >> 5);
    if (row >= rows) return;
    int lane = threadIdx.x & 31;
    const float* p = x + (size_t)row * D_DIM;
    float s = 0.f;
    #pragma unroll
    for (int c = lane; c < D_DIM; c += 32) { float v = p[c]; s += v * v; }
    #pragma unroll
    for (int o = 16; o; o >>= 1) s += __shfl_down_sync(0xffffffffu, s, o);
    if (lane == 0) out[row] = s;
}

// -------- fused distance-GEMM + argmin + gather --------
__global__ __launch_bounds__(NTHREADS)
void vq_argmin_kernel(const float* __restrict__ X, const float* __restrict__ E,
                      const float* __restrict__ xsq, const float* __restrict__ esq,
                      float* __restrict__ outq, float* __restrict__ outi,
                      int N, int K)
{
    __shared__ float Xs[BK][BM];
    __shared__ float Es[BK][BN];
    __shared__ float s_bd[16][BM];
    __shared__ int   s_bi[16][BM];
    __shared__ int   s_idx[BM];

    const int tid = threadIdx.x;
    const int tx = tid & 15;   // col group 0..15 -> cols tx*8..tx*8+7
    const int ty = tid >> 4;   // row group 0..7  -> rows ty*8..ty*8+7
    const int n0 = blockIdx.x * BM;

    float bestd[TM];
    int   besti[TM];
    float xq[TM];
    #pragma unroll
    for (int i = 0; i < TM; i++) {
        bestd[i] = 3.4e38f;
        besti[i] = 0x7fffffff;
        xq[i] = xsq[n0 + ty * TM + i];
    }

    for (int k0 = 0; k0 < K; k0 += BN) {
        float acc[TM][TN];
        #pragma unroll
        for (int i = 0; i < TM; i++)
            #pragma unroll
            for (int j = 0; j < TN; j++) acc[i][j] = 0.f;

        for (int d0 = 0; d0 < D_DIM; d0 += BK) {
            // X tile: 64 rows x 16 cols = 256 float4, 2 per thread
            #pragma unroll
            for (int l = 0; l < 2; l++) {
                int f  = tid + l * NTHREADS;     // 0..255
                int r  = f >> 2;                 // row 0..63
                int c4 = f & 3;                  // float4 slot within 16-wide row
                float4 v = *(const float4*)(X + (size_t)(n0 + r) * D_DIM + d0 + c4 * 4);
                Xs[c4 * 4 + 0][r] = v.x;
                Xs[c4 * 4 + 1][r] = v.y;
                Xs[c4 * 4 + 2][r] = v.z;
                Xs[c4 * 4 + 3][r] = v.w;
            }
            // E tile: 128 rows x 16 cols = 512 float4, 4 per thread
            #pragma unroll
            for (int l = 0; l < 4; l++) {
                int f  = tid + l * NTHREADS;     // 0..511
                int r  = f >> 2;                 // row 0..127
                int c4 = f & 3;
                float4 v = *(const float4*)(E + (size_t)(k0 + r) * D_DIM + d0 + c4 * 4);
                Es[c4 * 4 + 0][r] = v.x;
                Es[c4 * 4 + 1][r] = v.y;
                Es[c4 * 4 + 2][r] = v.z;
                Es[c4 * 4 + 3][r] = v.w;
            }
            __syncthreads();

            #pragma unroll
            for (int kk = 0; kk < BK; kk++) {
                float xr[TM], er[TN];
                #pragma unroll
                for (int i = 0; i < TM; i++) xr[i] = Xs[kk][ty * TM + i];
                #pragma unroll
                for (int j = 0; j < TN; j++) er[j] = Es[kk][tx * TN + j];
                #pragma unroll
                for (int i = 0; i < TM; i++)
                    #pragma unroll
                    for (int j = 0; j < TN; j++)
                        acc[i][j] = fmaf(xr[i], er[j], acc[i][j]);
            }
            __syncthreads();
        }

        // fold this 128-code tile into the running argmin
        #pragma unroll
        for (int i = 0; i < TM; i++) {
            #pragma unroll
            for (int j = 0; j < TN; j++) {
                int col = k0 + tx * TN + j;
                float d = xq[i] + esq[col] - 2.f * acc[i][j];
                if (d < bestd[i] || (d == bestd[i] && col < besti[i])) {
                    bestd[i] = d;
                    besti[i] = col;
                }
            }
        }
    }

    // cross-column-group reduction (16 candidates per row)
    #pragma unroll
    for (int i = 0; i < TM; i++) {
        s_bd[tx][ty * TM + i] = bestd[i];
        s_bi[tx][ty * TM + i] = besti[i];
    }
    __syncthreads();

    if (tid < BM) {
        float bd = s_bd[0][tid];
        int   bi = s_bi[0][tid];
        #pragma unroll
        for (int t = 1; t < 16; t++) {
            float d  = s_bd[t][tid];
            int   ii = s_bi[t][tid];
            if (d < bd || (d == bd && ii < bi)) { bd = d; bi = ii; }
        }
        s_idx[tid] = bi;
        outi[n0 + tid] = (float)bi;   // indices as float32 in concatenated output
    }
    __syncthreads();

    // gather embed[best] -> outq, 64 rows x 64 float4 = 4096 float4
    for (int f = tid; f < BM * (D_DIM / 4); f += NTHREADS) {
        int r  = f / (D_DIM / 4);
        int c4 = f % (D_DIM / 4);
        int bi = s_idx[r];
        float4 v = *(const float4*)(E + (size_t)bi * D_DIM + c4 * 4);
        *(float4*)(outq + (size_t)(n0 + r) * D_DIM + c4 * 4) = v;
    }
}

extern "C" void kernel_launch(void* const* d_in, const int* in_sizes, int n_in,
                              void* d_out, int out_size) {
    const float* X = (const float*)d_in[0];   // inputs_flatten [N, 256]
    const float* E = (const float*)d_in[1];   // embed [K, 256]
    const int N = in_sizes[0] / D_DIM;
    const int K = in_sizes[1] / D_DIM;

    float* p_xsq = nullptr;
    float* p_esq = nullptr;
    cudaGetSymbolAddress((void**)&p_xsq, g_xsq);
    cudaGetSymbolAddress((void**)&p_esq, g_esq);

    float* outq = (float*)d_out;                   // [N, 256]
    float* outi = (float*)d_out + (size_t)N * D_DIM; // [N] indices (as float)

    // sum of squares: warp per row, 8 warps per block
    {
        int wpb = 8, thr = 32 * wpb;
        sumsq_kernel<<<(N + wpb - 1) / wpb, thr>>>(X, p_xsq, N);
        sumsq_kernel<<<(K + wpb - 1) / wpb, thr>>>(E, p_esq, K);
    }

    vq_argmin_kernel<<<N / BM, NTHREADS>>>(X, E, p_xsq, p_esq, outq, outi, N, K);
}